// round 15
// baseline (speedup 1.0000x reference)
#include <cuda_runtime.h>
#include <cuda_fp16.h>
#include <cstdint>

// ---------------------------------------------------------------------------
// Problem constants
// ---------------------------------------------------------------------------
#define NW        192
#define BWIN      1536
#define NTOK      64
#define DIMC      192
#define HEADS     6
#define HDIM      32
#define M_TOT     (BWIN * NTOK)     // 98304
#define MTILES    (M_TOT / 128)     // 768  (KV kernel, M-tile 128)
#define MTILES64  (M_TOT / 64)      // 1536 (Q/out kernels, M-tile 64)

// scratch (fp16 pipeline buffers)
__device__ __half g_Qh[M_TOT * DIMC];
__device__ __half g_Kh[M_TOT * DIMC];
__device__ __half g_Vh[M_TOT * DIMC];
__device__ __half g_Oh[M_TOT * DIMC];
__device__ __half g_ADDh[NW * HEADS * 4096];

// ---------------------------------------------------------------------------
// stream/event plumbing
// ---------------------------------------------------------------------------
struct StreamPack {
    cudaStream_t s1 = nullptr;
    cudaEvent_t  eFork = nullptr, eJoin = nullptr;
    StreamPack() {
        cudaStreamCreateWithFlags(&s1, cudaStreamNonBlocking);
        cudaEventCreateWithFlags(&eFork, cudaEventDisableTiming);
        cudaEventCreateWithFlags(&eJoin, cudaEventDisableTiming);
    }
};
static StreamPack g_sp;

// ---------------------------------------------------------------------------
// helpers
// ---------------------------------------------------------------------------
__device__ __forceinline__ uint2 cvtH4(float4 v) {
    union { __half2 h; uint32_t u; } c0, c1;
    c0.h = __halves2half2(__float2half_rn(v.x), __float2half_rn(v.y));
    c1.h = __halves2half2(__float2half_rn(v.z), __float2half_rn(v.w));
    uint2 r; r.x = c0.u; r.y = c1.u; return r;
}
__device__ __forceinline__ uint32_t cvtH2(float p0, float p1) {
    union { __half2 h; uint32_t u; } c;
    c.h = __halves2half2(__float2half_rn(p0), __float2half_rn(p1));
    return c.u;
}
__device__ __forceinline__ void hmma(float* d, const uint32_t* a,
                                     uint32_t b0, uint32_t b1) {
    asm volatile(
        "mma.sync.aligned.m16n8k16.row.col.f32.f16.f16.f32 "
        "{%0,%1,%2,%3}, {%4,%5,%6,%7}, {%8,%9}, {%0,%1,%2,%3};"
        : "+f"(d[0]), "+f"(d[1]), "+f"(d[2]), "+f"(d[3])
        : "r"(a[0]), "r"(a[1]), "r"(a[2]), "r"(a[3]), "r"(b0), "r"(b1));
}
__device__ __forceinline__ void ldsm4(uint32_t& r0, uint32_t& r1,
                                      uint32_t& r2, uint32_t& r3, uint32_t addr) {
    asm volatile("ldmatrix.sync.aligned.m8n8.x4.shared.b16 {%0,%1,%2,%3}, [%4];"
                 : "=r"(r0), "=r"(r1), "=r"(r2), "=r"(r3) : "r"(addr));
}
__device__ __forceinline__ void ldsm4t(uint32_t& r0, uint32_t& r1,
                                       uint32_t& r2, uint32_t& r3, uint32_t addr) {
    asm volatile("ldmatrix.sync.aligned.m8n8.x4.trans.shared.b16 {%0,%1,%2,%3}, [%4];"
                 : "=r"(r0), "=r"(r1), "=r"(r2), "=r"(r3) : "r"(addr));
}
__device__ __forceinline__ uint32_t cvta_smem(const void* p) {
    return (uint32_t)__cvta_generic_to_shared(p);
}
__device__ __forceinline__ float2 h2f2(uint32_t u) {
    union { uint32_t u; __half2 h; } c; c.u = u;
    return __half22float2(c.h);
}

// ---------------------------------------------------------------------------
// bias table (fp16)
// ---------------------------------------------------------------------------
__global__ void __launch_bounds__(256)
addtable_kernel(const float* __restrict__ mask, const int* __restrict__ rpi,
                const float* __restrict__ rpb, __half* __restrict__ T)
{
    int idx = blockIdx.x * 256 + threadIdx.x;
    int i   = idx & 4095;
    int wh  = idx >> 12;
    int hd  = wh % HEADS;
    int w   = wh / HEADS;
    T[idx] = __float2half_rn(rpb[rpi[i] * HEADS + hd] + mask[w * 4096 + i]);
}

// ---------------------------------------------------------------------------
// HMMA GEMM (Q / out projection), M-tile 64, 256 threads, 2 CTAs/SM.
// Y = A @ (wscale*W)^T + wscale*bias
// IN_F16: A fp16, else fp32.  OUT_MODE: 0 fp32, 1 fp16.
// ---------------------------------------------------------------------------
#define WSTRIDE 200
#define ASTRIDE 104

#define SM_WHI   0
#define SM_A     (SM_WHI + 192 * WSTRIDE * 2)        // 76800
#define SM_BIAS  (SM_A   + 64 * ASTRIDE * 2)         // 90112
#define SM_TOTAL (SM_BIAS + 192 * 4)                 // 90880  (x2 = 181760 <= 228KB)

template<int IN_F16, int OUT_MODE>
__global__ void __launch_bounds__(256, 2)
gemm_hmma_kernel(const void* __restrict__ Ain, const float* __restrict__ W,
                 const float* __restrict__ bias, void* __restrict__ Y0,
                 float wscale)
{
    extern __shared__ char smem[];
    __half* whi = (__half*)(smem + SM_WHI);
    __half* ash = (__half*)(smem + SM_A);
    float*  bss = (float*) (smem + SM_BIAS);

    const int tid  = threadIdx.x;
    const int lane = tid & 31;
    const int warp = tid >> 5;           // 0..7
    const int wm   = warp & 1;           // 2 M sub-tiles of 32
    const int wn   = warp >> 1;          // 4 N groups of 48

    for (int i = tid; i < 192 * 48; i += 256) {
        int row = i / 48;
        int k4  = (i % 48) * 4;
        float4 v = *(const float4*)(W + (size_t)row * DIMC + k4);
        v.x *= wscale; v.y *= wscale; v.z *= wscale; v.w *= wscale;
        *(uint2*)(whi + row * WSTRIDE + k4) = cvtH4(v);
    }
    if (tid < DIMC) bss[tid] = bias[tid] * wscale;
    __syncthreads();

    const int fr  = lane >> 2;
    const int fc  = (lane & 3) * 2;
    const int l15 = lane & 15;
    const int lk8 = (lane >> 4) * 8;

    const uint32_t aA  = cvta_smem(ash) + (uint32_t)(((wm * 32 + l15) * ASTRIDE + lk8) * 2);
    const uint32_t aWh = cvta_smem(whi) + (uint32_t)(((wn * 48 + l15) * WSTRIDE + lk8) * 2);

    const float*  Af = (const float*) Ain;
    const __half* Ah = (const __half*)Ain;

    float4 pf[6];
    uint4  pg[3];
    int tile = blockIdx.x;
    if (tile < MTILES64) {
        if (IN_F16) {
#pragma unroll
            for (int j = 0; j < 3; j++) {
                int i = tid + j * 256;
                int row = i / 12, c8 = (i % 12) * 8;
                pg[j] = *(const uint4*)(Ah + (size_t)(tile * 64 + row) * DIMC + c8);
            }
        } else {
#pragma unroll
            for (int j = 0; j < 6; j++) {
                int i = tid + j * 256;
                int row = i / 24, c4 = (i % 24) * 4;
                pf[j] = *(const float4*)(Af + (size_t)(tile * 64 + row) * DIMC + c4);
            }
        }
    }

    for (; tile < MTILES64; tile += gridDim.x) {
        float acc[2][6][4];
#pragma unroll
        for (int mi = 0; mi < 2; mi++)
#pragma unroll
            for (int nt = 0; nt < 6; nt++)
#pragma unroll
                for (int j = 0; j < 4; j++) acc[mi][nt][j] = 0.f;

#pragma unroll 1
        for (int c = 0; c < 2; c++) {
            __syncthreads();
            if (IN_F16) {
#pragma unroll
                for (int j = 0; j < 3; j++) {
                    int i = tid + j * 256;
                    int row = i / 12, c8 = (i % 12) * 8;
                    *(uint4*)(ash + row * ASTRIDE + c8) = pg[j];
                }
            } else {
#pragma unroll
                for (int j = 0; j < 6; j++) {
                    int i = tid + j * 256;
                    int row = i / 24, c4 = (i % 24) * 4;
                    *(uint2*)(ash + row * ASTRIDE + c4) = cvtH4(pf[j]);
                }
            }
            __syncthreads();

            int nc = c + 1, ntile = tile;
            if (nc == 2) { nc = 0; ntile = tile + gridDim.x; }
            if (ntile < MTILES64) {
                if (IN_F16) {
#pragma unroll
                    for (int j = 0; j < 3; j++) {
                        int i = tid + j * 256;
                        int row = i / 12, c8 = (i % 12) * 8;
                        pg[j] = *(const uint4*)(Ah + (size_t)(ntile * 64 + row) * DIMC
                                                   + nc * 96 + c8);
                    }
                } else {
#pragma unroll
                    for (int j = 0; j < 6; j++) {
                        int i = tid + j * 256;
                        int row = i / 24, c4 = (i % 24) * 4;
                        pf[j] = *(const float4*)(Af + (size_t)(ntile * 64 + row) * DIMC
                                                    + nc * 96 + c4);
                    }
                }
            }

#pragma unroll
            for (int ks = 0; ks < 6; ks++) {
                const uint32_t kkb = (uint32_t)(ks * 16 * 2);
                const uint32_t kgb = (uint32_t)((c * 96 + ks * 16) * 2);
                uint32_t fa0[4], fa1[4];
                ldsm4(fa0[0], fa0[1], fa0[2], fa0[3], aA + kkb);
                ldsm4(fa1[0], fa1[1], fa1[2], fa1[3], aA + 16 * ASTRIDE * 2 + kkb);
#pragma unroll
                for (int ntp = 0; ntp < 3; ntp++) {
                    uint32_t h0, h1, h2, h3;
                    ldsm4(h0, h1, h2, h3, aWh + ntp * (16 * WSTRIDE * 2) + kgb);
                    hmma(acc[0][2*ntp  ], fa0, h0, h2);
                    hmma(acc[0][2*ntp+1], fa0, h1, h3);
                    hmma(acc[1][2*ntp  ], fa1, h0, h2);
                    hmma(acc[1][2*ntp+1], fa1, h1, h3);
                }
            }
        }

#pragma unroll
        for (int mi = 0; mi < 2; mi++) {
            int row = tile * 64 + wm * 32 + mi * 16 + fr;
#pragma unroll
            for (int nt = 0; nt < 6; nt++) {
                int col = wn * 48 + nt * 8 + fc;
                float2 bv = *(const float2*)&bss[col];
                float v0x = acc[mi][nt][0] + bv.x, v0y = acc[mi][nt][1] + bv.y;
                float v1x = acc[mi][nt][2] + bv.x, v1y = acc[mi][nt][3] + bv.y;
                size_t o0 = (size_t)row * DIMC + col;
                size_t o1 = (size_t)(row + 8) * DIMC + col;
                if (OUT_MODE == 0) {
                    float2 r0, r1;
                    r0.x = v0x; r0.y = v0y;  r1.x = v1x; r1.y = v1y;
                    *(float2*)((float*)Y0 + o0) = r0;
                    *(float2*)((float*)Y0 + o1) = r1;
                } else {
                    *(uint32_t*)((__half*)Y0 + o0) = cvtH2(v0x, v0y);
                    *(uint32_t*)((__half*)Y0 + o1) = cvtH2(v1x, v1y);
                }
            }
        }
    }
}

// ---------------------------------------------------------------------------
// Fused KV GEMM with half-tile register prefetch (unchanged from R14)
// ---------------------------------------------------------------------------
#define KV_WS    0
#define KV_A     (KV_WS + 384 * WSTRIDE * 2)          // 153600
#define KV_BIAS  (KV_A  + 128 * WSTRIDE * 2)          // 204800
#define KV_TOTAL (KV_BIAS + 384 * 4)                  // 206336

__global__ void __launch_bounds__(512, 1)
kvgemm_kernel(const float* __restrict__ px, const float* __restrict__ wkv,
              const float* __restrict__ bkv,
              __half* __restrict__ Kh, __half* __restrict__ Vh)
{
    extern __shared__ char smem[];
    __half* ws  = (__half*)(smem + KV_WS);
    __half* ash = (__half*)(smem + KV_A);
    float*  bss = (float*) (smem + KV_BIAS);

    const int tid  = threadIdx.x;
    const int lane = tid & 31;
    const int warp = tid >> 5;
    const int wm   = warp & 3;
    const int wn   = warp >> 2;

    for (int i = tid; i < 384 * 48; i += 512) {
        int row = i / 48;
        int k4  = (i % 48) * 4;
        float4 v = *(const float4*)(wkv + (size_t)row * DIMC + k4);
        *(uint2*)(ws + row * WSTRIDE + k4) = cvtH4(v);
    }
    if (tid < 384) bss[tid] = bkv[tid];

    const int fr  = lane >> 2;
    const int fc  = (lane & 3) * 2;
    const int l15 = lane & 15;
    const int lk8 = (lane >> 4) * 8;

    const uint32_t aA = cvta_smem(ash) + (uint32_t)(((wm * 32 + l15) * WSTRIDE + lk8) * 2);
    const uint32_t aW = cvta_smem(ws)  + (uint32_t)(((wn * 48 + l15) * WSTRIDE + lk8) * 2);

    int tile = blockIdx.x;
    if (tile < MTILES) {
#pragma unroll
        for (int j = 0; j < 12; j++) {
            int i = tid + j * 512;
            int row = i / 48, c4 = (i % 48) * 4;
            float4 v = *(const float4*)(px + (size_t)(tile * 128 + row) * DIMC + c4);
            *(uint2*)(ash + row * WSTRIDE + c4) = cvtH4(v);
        }
    }
    __syncthreads();

    for (; tile < MTILES; tile += gridDim.x) {
        const int ntile = tile + gridDim.x;

        // ---- K half ----
        {
            float acc[2][6][4];
#pragma unroll
            for (int mi = 0; mi < 2; mi++)
#pragma unroll
                for (int nt = 0; nt < 6; nt++)
#pragma unroll
                    for (int j = 0; j < 4; j++) acc[mi][nt][j] = 0.f;

#pragma unroll
            for (int ks = 0; ks < 12; ks++) {
                const uint32_t kkb = (uint32_t)(ks * 16 * 2);
                uint32_t fa0[4], fa1[4];
                ldsm4(fa0[0], fa0[1], fa0[2], fa0[3], aA + kkb);
                ldsm4(fa1[0], fa1[1], fa1[2], fa1[3], aA + 16 * WSTRIDE * 2 + kkb);
#pragma unroll
                for (int ntp = 0; ntp < 3; ntp++) {
                    uint32_t h0, h1, h2, h3;
                    ldsm4(h0, h1, h2, h3, aW + ntp * (16 * WSTRIDE * 2) + kkb);
                    hmma(acc[0][2*ntp  ], fa0, h0, h2);
                    hmma(acc[0][2*ntp+1], fa0, h1, h3);
                    hmma(acc[1][2*ntp  ], fa1, h0, h2);
                    hmma(acc[1][2*ntp+1], fa1, h1, h3);
                }
            }
#pragma unroll
            for (int mi = 0; mi < 2; mi++) {
                int row = tile * 128 + wm * 32 + mi * 16 + fr;
#pragma unroll
                for (int nt = 0; nt < 6; nt++) {
                    int col = wn * 48 + nt * 8 + fc;
                    float2 bv = *(const float2*)&bss[col];
                    size_t o0 = (size_t)row * DIMC + col;
                    size_t o1 = (size_t)(row + 8) * DIMC + col;
                    *(uint32_t*)(Kh + o0) = cvtH2(acc[mi][nt][0] + bv.x,
                                                  acc[mi][nt][1] + bv.y);
                    *(uint32_t*)(Kh + o1) = cvtH2(acc[mi][nt][2] + bv.x,
                                                  acc[mi][nt][3] + bv.y);
                }
            }
        }

        // ---- prefetch rows 0..63 of next tile ----
        float4 pf[6];
        if (ntile < MTILES) {
#pragma unroll
            for (int j = 0; j < 6; j++) {
                int i = tid + j * 512;
                int row = i / 48, c4 = (i % 48) * 4;
                pf[j] = *(const float4*)(px + (size_t)(ntile * 128 + row) * DIMC + c4);
            }
        }

        // ---- V half ----
        {
            const uint32_t wbase = aW + (uint32_t)(192 * WSTRIDE * 2);
            float acc[2][6][4];
#pragma unroll
            for (int mi = 0; mi < 2; mi++)
#pragma unroll
                for (int nt = 0; nt < 6; nt++)
#pragma unroll
                    for (int j = 0; j < 4; j++) acc[mi][nt][j] = 0.f;

#pragma unroll
            for (int ks = 0; ks < 12; ks++) {
                const uint32_t kkb = (uint32_t)(ks * 16 * 2);
                uint32_t fa0[4], fa1[4];
                ldsm4(fa0[0], fa0[1], fa0[2], fa0[3], aA + kkb);
                ldsm4(fa1[0], fa1[1], fa1[2], fa1[3], aA + 16 * WSTRIDE * 2 + kkb);
#pragma unroll
                for (int ntp = 0; ntp < 3; ntp++) {
                    uint32_t h0, h1, h2, h3;
                    ldsm4(h0, h1, h2, h3, wbase + ntp * (16 * WSTRIDE * 2) + kkb);
                    hmma(acc[0][2*ntp  ], fa0, h0, h2);
                    hmma(acc[0][2*ntp+1], fa0, h1, h3);
                    hmma(acc[1][2*ntp  ], fa1, h0, h2);
                    hmma(acc[1][2*ntp+1], fa1, h1, h3);
                }
            }
#pragma unroll
            for (int mi = 0; mi < 2; mi++) {
                int row = tile * 128 + wm * 32 + mi * 16 + fr;
#pragma unroll
                for (int nt = 0; nt < 6; nt++) {
                    int col = wn * 48 + nt * 8 + fc;
                    float2 bv = *(const float2*)&bss[192 + col];
                    size_t o0 = (size_t)row * DIMC + col;
                    size_t o1 = (size_t)(row + 8) * DIMC + col;
                    *(uint32_t*)(Vh + o0) = cvtH2(acc[mi][nt][0] + bv.x,
                                                  acc[mi][nt][1] + bv.y);
                    *(uint32_t*)(Vh + o1) = cvtH2(acc[mi][nt][2] + bv.x,
                                                  acc[mi][nt][3] + bv.y);
                }
            }
        }

        __syncthreads();
        if (ntile < MTILES) {
#pragma unroll
            for (int j = 0; j < 6; j++) {
                int i = tid + j * 512;
                int row = i / 48, c4 = (i % 48) * 4;
                *(uint2*)(ash + row * WSTRIDE + c4) = cvtH4(pf[j]);
            }
#pragma unroll
            for (int j = 0; j < 6; j++) {
                int i = tid + j * 512;
                int row = 64 + i / 48, c4 = (i % 48) * 4;
                float4 v = *(const float4*)(px + (size_t)(ntile * 128 + row) * DIMC + c4);
                *(uint2*)(ash + row * WSTRIDE + c4) = cvtH4(v);
            }
        }
        __syncthreads();
    }
}

// ---------------------------------------------------------------------------
// HMMA attention: 384 threads, 2 units per warp, 2 blocks/SM (unchanged)
// ---------------------------------------------------------------------------
#define KSTR 200

#define AT_KH 0
#define AT_VH (AT_KH + 64 * KSTR * 2)
#define AT_TOTAL (AT_VH + 64 * KSTR * 2)    // 51200 B

__global__ void __launch_bounds__(384, 2)
attn_hmma_kernel(const __half* __restrict__ Qh, const __half* __restrict__ Kh,
                 const __half* __restrict__ Vh, const __half* __restrict__ ADDT,
                 __half* __restrict__ Oh)
{
    extern __shared__ char smem[];
    __half* khs = (__half*)(smem + AT_KH);
    __half* vhs = (__half*)(smem + AT_VH);

    const int b   = blockIdx.x;
    const int w   = b % NW;
    const int tid = threadIdx.x;

    for (int i = tid; i < 1536; i += 384) {
        int row = i / 24, c8 = (i % 24) * 8;
        size_t src = (size_t)(b * 64 + row) * DIMC + c8;
        int    dst = row * KSTR + c8;
        *(uint4*)(khs + dst) = *(const uint4*)(Kh + src);
        *(uint4*)(vhs + dst) = *(const uint4*)(Vh + src);
    }
    __syncthreads();

    const int warp = tid >> 5;
    const int lane = tid & 31;
    const int fr   = lane >> 2;
    const int fc   = (lane & 3) * 2;
    const int l15  = lane & 15;
    const int lk8  = (lane >> 4) * 8;

    const uint32_t aKh = cvta_smem(khs) + (uint32_t)((l15 * KSTR + lk8) * 2);

#pragma unroll 1
    for (int uu = 0; uu < 2; uu++) {
        const int unit = warp * 2 + uu;
        const int hd   = unit >> 2;
        const int mt   = unit & 3;
        const int r0   = mt * 16 + fr;
        const int kb   = hd * 32;

        const uint32_t vln = (uint32_t)((((lane & 7) + ((lane >> 4) & 1) * 8) * KSTR
                                         + ((lane >> 3) & 1) * 8 + kb) * 2);
        const uint32_t aVh = cvta_smem(vhs) + vln;

        float acc[8][4];
#pragma unroll
        for (int nt = 0; nt < 8; nt++)
#pragma unroll
            for (int j = 0; j < 4; j++) acc[nt][j] = 0.f;

        const __half* qbase = Qh + (size_t)(b * 64 + r0) * DIMC;
#pragma unroll
        for (int ks = 0; ks < 2; ks++) {
            const int kk = kb + ks * 16;
            uint32_t ah[4];
            ah[0] = *(const uint32_t*)(qbase + kk + fc);
            ah[1] = *(const uint32_t*)(qbase + 8 * DIMC + kk + fc);
            ah[2] = *(const uint32_t*)(qbase + kk + 8 + fc);
            ah[3] = *(const uint32_t*)(qbase + 8 * DIMC + kk + 8 + fc);
            const uint32_t kkb = (uint32_t)(kk * 2);
#pragma unroll
            for (int ntp = 0; ntp < 4; ntp++) {
                uint32_t h0, h1, h2, h3;
                ldsm4(h0, h1, h2, h3, aKh + ntp * (16 * KSTR * 2) + kkb);
                hmma(acc[2*ntp  ], ah, h0, h2);
                hmma(acc[2*ntp+1], ah, h1, h3);
            }
        }

        const __half* T = ADDT + ((size_t)(w * HEADS + hd)) * 4096;
#pragma unroll
        for (int nt = 0; nt < 8; nt++) {
            int cc = nt * 8 + fc;
            float2 t0 = h2f2(*(const uint32_t*)(T + (r0    ) * 64 + cc));
            float2 t1 = h2f2(*(const uint32_t*)(T + (r0 + 8) * 64 + cc));
            acc[nt][0] += t0.x;  acc[nt][1] += t0.y;
            acc[nt][2] += t1.x;  acc[nt][3] += t1.y;
        }

        float m0 = -1e30f, m1 = -1e30f;
#pragma unroll
        for (int nt = 0; nt < 8; nt++) {
            m0 = fmaxf(m0, fmaxf(acc[nt][0], acc[nt][1]));
            m1 = fmaxf(m1, fmaxf(acc[nt][2], acc[nt][3]));
        }
        m0 = fmaxf(m0, __shfl_xor_sync(0xffffffffu, m0, 1));
        m0 = fmaxf(m0, __shfl_xor_sync(0xffffffffu, m0, 2));
        m1 = fmaxf(m1, __shfl_xor_sync(0xffffffffu, m1, 1));
        m1 = fmaxf(m1, __shfl_xor_sync(0xffffffffu, m1, 2));

        float s0 = 0.f, s1 = 0.f;
#pragma unroll
        for (int nt = 0; nt < 8; nt++) {
            acc[nt][0] = __expf(acc[nt][0] - m0);  s0 += acc[nt][0];
            acc[nt][1] = __expf(acc[nt][1] - m0);  s0 += acc[nt][1];
            acc[nt][2] = __expf(acc[nt][2] - m1);  s1 += acc[nt][2];
            acc[nt][3] = __expf(acc[nt][3] - m1);  s1 += acc[nt][3];
        }
        s0 += __shfl_xor_sync(0xffffffffu, s0, 1);
        s0 += __shfl_xor_sync(0xffffffffu, s0, 2);
        s1 += __shfl_xor_sync(0xffffffffu, s1, 1);
        s1 += __shfl_xor_sync(0xffffffffu, s1, 2);
        float i0 = 1.f / s0, i1 = 1.f / s1;

        uint32_t ph[4][4];
#pragma unroll
        for (int kt = 0; kt < 4; kt++) {
            ph[kt][0] = cvtH2(acc[2*kt  ][0] * i0, acc[2*kt  ][1] * i0);
            ph[kt][1] = cvtH2(acc[2*kt  ][2] * i1, acc[2*kt  ][3] * i1);
            ph[kt][2] = cvtH2(acc[2*kt+1][0] * i0, acc[2*kt+1][1] * i0);
            ph[kt][3] = cvtH2(acc[2*kt+1][2] * i1, acc[2*kt+1][3] * i1);
        }

        float oacc[4][4];
#pragma unroll
        for (int dt = 0; dt < 4; dt++)
#pragma unroll
            for (int j = 0; j < 4; j++) oacc[dt][j] = 0.f;

#pragma unroll
        for (int kt = 0; kt < 4; kt++) {
            const uint32_t kof = (uint32_t)(kt * 16 * KSTR * 2);
#pragma unroll
            for (int p = 0; p < 2; p++) {
                const uint32_t off = kof + (uint32_t)(p * 16 * 2);
                uint32_t h0, h1, h2, h3;
                ldsm4t(h0, h1, h2, h3, aVh + off);
                hmma(oacc[2*p  ], ph[kt], h0, h2);
                hmma(oacc[2*p+1], ph[kt], h1, h3);
            }
        }

#pragma unroll
        for (int dt = 0; dt < 4; dt++) {
            int col = kb + dt * 8 + fc;
            *(uint32_t*)(Oh + (size_t)(b * 64 + r0    ) * DIMC + col) =
                cvtH2(oacc[dt][0], oacc[dt][1]);
            *(uint32_t*)(Oh + (size_t)(b * 64 + r0 + 8) * DIMC + col) =
                cvtH2(oacc[dt][2], oacc[dt][3]);
        }
    }
}

// ---------------------------------------------------------------------------
// launcher
// ---------------------------------------------------------------------------
extern "C" void kernel_launch(void* const* d_in, const int* in_sizes, int n_in,
                              void* d_out, int out_size)
{
    const float* x    = (const float*)d_in[0];
    const float* px   = (const float*)d_in[1];
    const float* mask = (const float*)d_in[2];
    const int*   rpi  = (const int*)  d_in[3];
    const float* rpb  = (const float*)d_in[4];
    const float* wq   = (const float*)d_in[5];
    const float* bq   = (const float*)d_in[6];
    const float* wkv  = (const float*)d_in[7];
    const float* bkv  = (const float*)d_in[8];
    const float* wp   = (const float*)d_in[9];
    const float* bp   = (const float*)d_in[10];
    float* out = (float*)d_out;

    __half *qh, *kh, *vh, *oh, *addt;
    cudaGetSymbolAddress((void**)&qh,  g_Qh);
    cudaGetSymbolAddress((void**)&kh,  g_Kh);
    cudaGetSymbolAddress((void**)&vh,  g_Vh);
    cudaGetSymbolAddress((void**)&oh,  g_Oh);
    cudaGetSymbolAddress((void**)&addt, g_ADDh);

    cudaFuncSetAttribute(gemm_hmma_kernel<0,1>,
                         cudaFuncAttributeMaxDynamicSharedMemorySize, SM_TOTAL);
    cudaFuncSetAttribute(gemm_hmma_kernel<1,0>,
                         cudaFuncAttributeMaxDynamicSharedMemorySize, SM_TOTAL);
    cudaFuncSetAttribute(kvgemm_kernel,
                         cudaFuncAttributeMaxDynamicSharedMemorySize, KV_TOTAL);
    cudaFuncSetAttribute(attn_hmma_kernel,
                         cudaFuncAttributeMaxDynamicSharedMemorySize, AT_TOTAL);

    const float qscale = 0.17677669529663687f;   // 1/sqrt(32)

    // ---- fork: Q path on s1, KV path on main stream ----
    cudaEventRecord(g_sp.eFork, 0);
    cudaStreamWaitEvent(g_sp.s1, g_sp.eFork, 0);

    addtable_kernel<<<NW * HEADS * 4096 / 256, 256, 0, g_sp.s1>>>(mask, rpi, rpb, addt);
    gemm_hmma_kernel<0,1><<<304, 256, SM_TOTAL, g_sp.s1>>>(x, wq, bq, qh, qscale);

    kvgemm_kernel<<<152, 512, KV_TOTAL>>>(px, wkv, bkv, kh, vh);

    // ---- join ----
    cudaEventRecord(g_sp.eJoin, g_sp.s1);
    cudaStreamWaitEvent(0, g_sp.eJoin, 0);

    // attention (fp16 in/out), 2 blocks/SM
    attn_hmma_kernel<<<BWIN, 384, AT_TOTAL>>>(qh, kh, vh, addt, oh);
    // out = O @ wp^T + bp  (fp16 A in, fp32 out), 2 CTAs/SM
    gemm_hmma_kernel<1,0><<<304, 256, SM_TOTAL>>>(oh, wp, bp, out, 1.0f);
}

// round 16
// speedup vs baseline: 1.3770x; 1.3770x over previous
#include <cuda_runtime.h>
#include <cuda_fp16.h>
#include <cstdint>

// ---------------------------------------------------------------------------
// Problem constants
// ---------------------------------------------------------------------------
#define NW        192
#define BWIN      1536
#define NTOK      64
#define DIMC      192
#define HEADS     6
#define HDIM      32
#define M_TOT     (BWIN * NTOK)     // 98304
#define MTILES    (M_TOT / 128)     // 768

// scratch (fp16 pipeline buffers)
__device__ __half g_Qh[M_TOT * DIMC];
__device__ __half g_Kh[M_TOT * DIMC];
__device__ __half g_Vh[M_TOT * DIMC];
__device__ __half g_Oh[M_TOT * DIMC];
__device__ __half g_ADDh[NW * HEADS * 4096];

// ---------------------------------------------------------------------------
// stream/event plumbing (created once at load; identical op sequence per call)
// ---------------------------------------------------------------------------
struct StreamPack {
    cudaStream_t s1 = nullptr;
    cudaEvent_t  eFork = nullptr, eJoin = nullptr;
    StreamPack() {
        cudaStreamCreateWithFlags(&s1, cudaStreamNonBlocking);
        cudaEventCreateWithFlags(&eFork, cudaEventDisableTiming);
        cudaEventCreateWithFlags(&eJoin, cudaEventDisableTiming);
    }
};
static StreamPack g_sp;

// ---------------------------------------------------------------------------
// helpers
// ---------------------------------------------------------------------------
__device__ __forceinline__ uint2 cvtH4(float4 v) {
    union { __half2 h; uint32_t u; } c0, c1;
    c0.h = __halves2half2(__float2half_rn(v.x), __float2half_rn(v.y));
    c1.h = __halves2half2(__float2half_rn(v.z), __float2half_rn(v.w));
    uint2 r; r.x = c0.u; r.y = c1.u; return r;
}
__device__ __forceinline__ uint32_t cvtH2(float p0, float p1) {
    union { __half2 h; uint32_t u; } c;
    c.h = __halves2half2(__float2half_rn(p0), __float2half_rn(p1));
    return c.u;
}
__device__ __forceinline__ void hmma(float* d, const uint32_t* a,
                                     uint32_t b0, uint32_t b1) {
    asm volatile(
        "mma.sync.aligned.m16n8k16.row.col.f32.f16.f16.f32 "
        "{%0,%1,%2,%3}, {%4,%5,%6,%7}, {%8,%9}, {%0,%1,%2,%3};"
        : "+f"(d[0]), "+f"(d[1]), "+f"(d[2]), "+f"(d[3])
        : "r"(a[0]), "r"(a[1]), "r"(a[2]), "r"(a[3]), "r"(b0), "r"(b1));
}
__device__ __forceinline__ void ldsm4(uint32_t& r0, uint32_t& r1,
                                      uint32_t& r2, uint32_t& r3, uint32_t addr) {
    asm volatile("ldmatrix.sync.aligned.m8n8.x4.shared.b16 {%0,%1,%2,%3}, [%4];"
                 : "=r"(r0), "=r"(r1), "=r"(r2), "=r"(r3) : "r"(addr));
}
__device__ __forceinline__ void ldsm4t(uint32_t& r0, uint32_t& r1,
                                       uint32_t& r2, uint32_t& r3, uint32_t addr) {
    asm volatile("ldmatrix.sync.aligned.m8n8.x4.trans.shared.b16 {%0,%1,%2,%3}, [%4];"
                 : "=r"(r0), "=r"(r1), "=r"(r2), "=r"(r3) : "r"(addr));
}
__device__ __forceinline__ uint32_t cvta_smem(const void* p) {
    return (uint32_t)__cvta_generic_to_shared(p);
}
__device__ __forceinline__ float2 h2f2(uint32_t u) {
    union { uint32_t u; __half2 h; } c; c.u = u;
    return __half22float2(c.h);
}

// ---------------------------------------------------------------------------
// bias table (fp16)
// ---------------------------------------------------------------------------
__global__ void __launch_bounds__(256)
addtable_kernel(const float* __restrict__ mask, const int* __restrict__ rpi,
                const float* __restrict__ rpb, __half* __restrict__ T)
{
    int idx = blockIdx.x * 256 + threadIdx.x;
    int i   = idx & 4095;
    int wh  = idx >> 12;
    int hd  = wh % HEADS;
    int w   = wh / HEADS;
    T[idx] = __float2half_rn(rpb[rpi[i] * HEADS + hd] + mask[w * 4096 + i]);
}

// ---------------------------------------------------------------------------
// HMMA GEMM (Q / out projection): Y = A @ (wscale*W)^T + wscale*bias
// M-tile 128, 512 threads, 1 CTA/SM (validated best config).
// IN_F16: A fp16, else fp32.  OUT_MODE: 0 fp32, 1 fp16.
// ---------------------------------------------------------------------------
#define WSTRIDE 200
#define ASTRIDE 104

#define SM_WHI   0
#define SM_A     (SM_WHI + 192 * WSTRIDE * 2)        // 76800
#define SM_BIAS  (SM_A   + 128 * ASTRIDE * 2)        // 103424
#define SM_TOTAL (SM_BIAS + 192 * 4)                 // 104192

template<int IN_F16, int OUT_MODE>
__global__ void __launch_bounds__(512, 1)
gemm_hmma_kernel(const void* __restrict__ Ain, const float* __restrict__ W,
                 const float* __restrict__ bias, void* __restrict__ Y0,
                 float wscale)
{
    extern __shared__ char smem[];
    __half* whi = (__half*)(smem + SM_WHI);
    __half* ash = (__half*)(smem + SM_A);
    float*  bss = (float*) (smem + SM_BIAS);

    const int tid  = threadIdx.x;
    const int lane = tid & 31;
    const int warp = tid >> 5;
    const int wm   = warp & 3;
    const int wn   = warp >> 2;

    for (int i = tid; i < 192 * 48; i += 512) {
        int row = i / 48;
        int k4  = (i % 48) * 4;
        float4 v = *(const float4*)(W + (size_t)row * DIMC + k4);
        v.x *= wscale; v.y *= wscale; v.z *= wscale; v.w *= wscale;
        *(uint2*)(whi + row * WSTRIDE + k4) = cvtH4(v);
    }
    if (tid < DIMC) bss[tid] = bias[tid] * wscale;
    __syncthreads();

    const int fr  = lane >> 2;
    const int fc  = (lane & 3) * 2;
    const int l15 = lane & 15;
    const int lk8 = (lane >> 4) * 8;

    const uint32_t aA  = cvta_smem(ash) + (uint32_t)(((wm * 32 + l15) * ASTRIDE + lk8) * 2);
    const uint32_t aWh = cvta_smem(whi) + (uint32_t)(((wn * 48 + l15) * WSTRIDE + lk8) * 2);

    const float*  Af = (const float*) Ain;
    const __half* Ah = (const __half*)Ain;

    float4 pf[6];
    uint4  pg[3];
    int tile = blockIdx.x;
    if (tile < MTILES) {
        if (IN_F16) {
#pragma unroll
            for (int j = 0; j < 3; j++) {
                int i = tid + j * 512;
                int row = i / 12, c8 = (i % 12) * 8;
                pg[j] = *(const uint4*)(Ah + (size_t)(tile * 128 + row) * DIMC + c8);
            }
        } else {
#pragma unroll
            for (int j = 0; j < 6; j++) {
                int i = tid + j * 512;
                int row = i / 24, c4 = (i % 24) * 4;
                pf[j] = *(const float4*)(Af + (size_t)(tile * 128 + row) * DIMC + c4);
            }
        }
    }

    for (; tile < MTILES; tile += gridDim.x) {
        float acc[2][6][4];
#pragma unroll
        for (int mi = 0; mi < 2; mi++)
#pragma unroll
            for (int nt = 0; nt < 6; nt++)
#pragma unroll
                for (int j = 0; j < 4; j++) acc[mi][nt][j] = 0.f;

#pragma unroll 1
        for (int c = 0; c < 2; c++) {
            __syncthreads();
            if (IN_F16) {
#pragma unroll
                for (int j = 0; j < 3; j++) {
                    int i = tid + j * 512;
                    int row = i / 12, c8 = (i % 12) * 8;
                    *(uint4*)(ash + row * ASTRIDE + c8) = pg[j];
                }
            } else {
#pragma unroll
                for (int j = 0; j < 6; j++) {
                    int i = tid + j * 512;
                    int row = i / 24, c4 = (i % 24) * 4;
                    *(uint2*)(ash + row * ASTRIDE + c4) = cvtH4(pf[j]);
                }
            }
            __syncthreads();

            int nc = c + 1, ntile = tile;
            if (nc == 2) { nc = 0; ntile = tile + gridDim.x; }
            if (ntile < MTILES) {
                if (IN_F16) {
#pragma unroll
                    for (int j = 0; j < 3; j++) {
                        int i = tid + j * 512;
                        int row = i / 12, c8 = (i % 12) * 8;
                        pg[j] = *(const uint4*)(Ah + (size_t)(ntile * 128 + row) * DIMC
                                                   + nc * 96 + c8);
                    }
                } else {
#pragma unroll
                    for (int j = 0; j < 6; j++) {
                        int i = tid + j * 512;
                        int row = i / 24, c4 = (i % 24) * 4;
                        pf[j] = *(const float4*)(Af + (size_t)(ntile * 128 + row) * DIMC
                                                    + nc * 96 + c4);
                    }
                }
            }

#pragma unroll
            for (int ks = 0; ks < 6; ks++) {
                const uint32_t kkb = (uint32_t)(ks * 16 * 2);
                const uint32_t kgb = (uint32_t)((c * 96 + ks * 16) * 2);
                uint32_t fa0[4], fa1[4];
                ldsm4(fa0[0], fa0[1], fa0[2], fa0[3], aA + kkb);
                ldsm4(fa1[0], fa1[1], fa1[2], fa1[3], aA + 16 * ASTRIDE * 2 + kkb);
#pragma unroll
                for (int ntp = 0; ntp < 3; ntp++) {
                    uint32_t h0, h1, h2, h3;
                    ldsm4(h0, h1, h2, h3, aWh + ntp * (16 * WSTRIDE * 2) + kgb);
                    hmma(acc[0][2*ntp  ], fa0, h0, h2);
                    hmma(acc[0][2*ntp+1], fa0, h1, h3);
                    hmma(acc[1][2*ntp  ], fa1, h0, h2);
                    hmma(acc[1][2*ntp+1], fa1, h1, h3);
                }
            }
        }

#pragma unroll
        for (int mi = 0; mi < 2; mi++) {
            int row = tile * 128 + wm * 32 + mi * 16 + fr;
#pragma unroll
            for (int nt = 0; nt < 6; nt++) {
                int col = wn * 48 + nt * 8 + fc;
                float2 bv = *(const float2*)&bss[col];
                float v0x = acc[mi][nt][0] + bv.x, v0y = acc[mi][nt][1] + bv.y;
                float v1x = acc[mi][nt][2] + bv.x, v1y = acc[mi][nt][3] + bv.y;
                size_t o0 = (size_t)row * DIMC + col;
                size_t o1 = (size_t)(row + 8) * DIMC + col;
                if (OUT_MODE == 0) {
                    float2 r0, r1;
                    r0.x = v0x; r0.y = v0y;  r1.x = v1x; r1.y = v1y;
                    *(float2*)((float*)Y0 + o0) = r0;
                    *(float2*)((float*)Y0 + o1) = r1;
                } else {
                    *(uint32_t*)((__half*)Y0 + o0) = cvtH2(v0x, v0y);
                    *(uint32_t*)((__half*)Y0 + o1) = cvtH2(v1x, v1y);
                }
            }
        }
    }
}

// ---------------------------------------------------------------------------
// Fused KV GEMM with half-tile register prefetch
// ---------------------------------------------------------------------------
#define KV_WS    0
#define KV_A     (KV_WS + 384 * WSTRIDE * 2)          // 153600
#define KV_BIAS  (KV_A  + 128 * WSTRIDE * 2)          // 204800
#define KV_TOTAL (KV_BIAS + 384 * 4)                  // 206336

__global__ void __launch_bounds__(512, 1)
kvgemm_kernel(const float* __restrict__ px, const float* __restrict__ wkv,
              const float* __restrict__ bkv,
              __half* __restrict__ Kh, __half* __restrict__ Vh)
{
    extern __shared__ char smem[];
    __half* ws  = (__half*)(smem + KV_WS);
    __half* ash = (__half*)(smem + KV_A);
    float*  bss = (float*) (smem + KV_BIAS);

    const int tid  = threadIdx.x;
    const int lane = tid & 31;
    const int warp = tid >> 5;
    const int wm   = warp & 3;
    const int wn   = warp >> 2;

    for (int i = tid; i < 384 * 48; i += 512) {
        int row = i / 48;
        int k4  = (i % 48) * 4;
        float4 v = *(const float4*)(wkv + (size_t)row * DIMC + k4);
        *(uint2*)(ws + row * WSTRIDE + k4) = cvtH4(v);
    }
    if (tid < 384) bss[tid] = bkv[tid];

    const int fr  = lane >> 2;
    const int fc  = (lane & 3) * 2;
    const int l15 = lane & 15;
    const int lk8 = (lane >> 4) * 8;

    const uint32_t aA = cvta_smem(ash) + (uint32_t)(((wm * 32 + l15) * WSTRIDE + lk8) * 2);
    const uint32_t aW = cvta_smem(ws)  + (uint32_t)(((wn * 48 + l15) * WSTRIDE + lk8) * 2);

    int tile = blockIdx.x;
    if (tile < MTILES) {
#pragma unroll
        for (int j = 0; j < 12; j++) {
            int i = tid + j * 512;
            int row = i / 48, c4 = (i % 48) * 4;
            float4 v = *(const float4*)(px + (size_t)(tile * 128 + row) * DIMC + c4);
            *(uint2*)(ash + row * WSTRIDE + c4) = cvtH4(v);
        }
    }
    __syncthreads();

    for (; tile < MTILES; tile += gridDim.x) {
        const int ntile = tile + gridDim.x;

        // ---- K half ----
        {
            float acc[2][6][4];
#pragma unroll
            for (int mi = 0; mi < 2; mi++)
#pragma unroll
                for (int nt = 0; nt < 6; nt++)
#pragma unroll
                    for (int j = 0; j < 4; j++) acc[mi][nt][j] = 0.f;

#pragma unroll
            for (int ks = 0; ks < 12; ks++) {
                const uint32_t kkb = (uint32_t)(ks * 16 * 2);
                uint32_t fa0[4], fa1[4];
                ldsm4(fa0[0], fa0[1], fa0[2], fa0[3], aA + kkb);
                ldsm4(fa1[0], fa1[1], fa1[2], fa1[3], aA + 16 * WSTRIDE * 2 + kkb);
#pragma unroll
                for (int ntp = 0; ntp < 3; ntp++) {
                    uint32_t h0, h1, h2, h3;
                    ldsm4(h0, h1, h2, h3, aW + ntp * (16 * WSTRIDE * 2) + kkb);
                    hmma(acc[0][2*ntp  ], fa0, h0, h2);
                    hmma(acc[0][2*ntp+1], fa0, h1, h3);
                    hmma(acc[1][2*ntp  ], fa1, h0, h2);
                    hmma(acc[1][2*ntp+1], fa1, h1, h3);
                }
            }
#pragma unroll
            for (int mi = 0; mi < 2; mi++) {
                int row = tile * 128 + wm * 32 + mi * 16 + fr;
#pragma unroll
                for (int nt = 0; nt < 6; nt++) {
                    int col = wn * 48 + nt * 8 + fc;
                    float2 bv = *(const float2*)&bss[col];
                    size_t o0 = (size_t)row * DIMC + col;
                    size_t o1 = (size_t)(row + 8) * DIMC + col;
                    *(uint32_t*)(Kh + o0) = cvtH2(acc[mi][nt][0] + bv.x,
                                                  acc[mi][nt][1] + bv.y);
                    *(uint32_t*)(Kh + o1) = cvtH2(acc[mi][nt][2] + bv.x,
                                                  acc[mi][nt][3] + bv.y);
                }
            }
        }

        // ---- prefetch rows 0..63 of next tile ----
        float4 pf[6];
        if (ntile < MTILES) {
#pragma unroll
            for (int j = 0; j < 6; j++) {
                int i = tid + j * 512;
                int row = i / 48, c4 = (i % 48) * 4;
                pf[j] = *(const float4*)(px + (size_t)(ntile * 128 + row) * DIMC + c4);
            }
        }

        // ---- V half ----
        {
            const uint32_t wbase = aW + (uint32_t)(192 * WSTRIDE * 2);
            float acc[2][6][4];
#pragma unroll
            for (int mi = 0; mi < 2; mi++)
#pragma unroll
                for (int nt = 0; nt < 6; nt++)
#pragma unroll
                    for (int j = 0; j < 4; j++) acc[mi][nt][j] = 0.f;

#pragma unroll
            for (int ks = 0; ks < 12; ks++) {
                const uint32_t kkb = (uint32_t)(ks * 16 * 2);
                uint32_t fa0[4], fa1[4];
                ldsm4(fa0[0], fa0[1], fa0[2], fa0[3], aA + kkb);
                ldsm4(fa1[0], fa1[1], fa1[2], fa1[3], aA + 16 * WSTRIDE * 2 + kkb);
#pragma unroll
                for (int ntp = 0; ntp < 3; ntp++) {
                    uint32_t h0, h1, h2, h3;
                    ldsm4(h0, h1, h2, h3, wbase + ntp * (16 * WSTRIDE * 2) + kkb);
                    hmma(acc[0][2*ntp  ], fa0, h0, h2);
                    hmma(acc[0][2*ntp+1], fa0, h1, h3);
                    hmma(acc[1][2*ntp  ], fa1, h0, h2);
                    hmma(acc[1][2*ntp+1], fa1, h1, h3);
                }
            }
#pragma unroll
            for (int mi = 0; mi < 2; mi++) {
                int row = tile * 128 + wm * 32 + mi * 16 + fr;
#pragma unroll
                for (int nt = 0; nt < 6; nt++) {
                    int col = wn * 48 + nt * 8 + fc;
                    float2 bv = *(const float2*)&bss[192 + col];
                    size_t o0 = (size_t)row * DIMC + col;
                    size_t o1 = (size_t)(row + 8) * DIMC + col;
                    *(uint32_t*)(Vh + o0) = cvtH2(acc[mi][nt][0] + bv.x,
                                                  acc[mi][nt][1] + bv.y);
                    *(uint32_t*)(Vh + o1) = cvtH2(acc[mi][nt][2] + bv.x,
                                                  acc[mi][nt][3] + bv.y);
                }
            }
        }

        __syncthreads();
        if (ntile < MTILES) {
#pragma unroll
            for (int j = 0; j < 6; j++) {
                int i = tid + j * 512;
                int row = i / 48, c4 = (i % 48) * 4;
                *(uint2*)(ash + row * WSTRIDE + c4) = cvtH4(pf[j]);
            }
#pragma unroll
            for (int j = 0; j < 6; j++) {
                int i = tid + j * 512;
                int row = 64 + i / 48, c4 = (i % 48) * 4;
                float4 v = *(const float4*)(px + (size_t)(ntile * 128 + row) * DIMC + c4);
                *(uint2*)(ash + row * WSTRIDE + c4) = cvtH4(v);
            }
        }
        __syncthreads();
    }
}

// ---------------------------------------------------------------------------
// HMMA attention: 384 threads, 2 units per warp, 2 blocks/SM
// ---------------------------------------------------------------------------
#define KSTR 200

#define AT_KH 0
#define AT_VH (AT_KH + 64 * KSTR * 2)
#define AT_TOTAL (AT_VH + 64 * KSTR * 2)    // 51200 B

__global__ void __launch_bounds__(384, 2)
attn_hmma_kernel(const __half* __restrict__ Qh, const __half* __restrict__ Kh,
                 const __half* __restrict__ Vh, const __half* __restrict__ ADDT,
                 __half* __restrict__ Oh)
{
    extern __shared__ char smem[];
    __half* khs = (__half*)(smem + AT_KH);
    __half* vhs = (__half*)(smem + AT_VH);

    const int b   = blockIdx.x;
    const int w   = b % NW;
    const int tid = threadIdx.x;

    for (int i = tid; i < 1536; i += 384) {
        int row = i / 24, c8 = (i % 24) * 8;
        size_t src = (size_t)(b * 64 + row) * DIMC + c8;
        int    dst = row * KSTR + c8;
        *(uint4*)(khs + dst) = *(const uint4*)(Kh + src);
        *(uint4*)(vhs + dst) = *(const uint4*)(Vh + src);
    }
    __syncthreads();

    const int warp = tid >> 5;
    const int lane = tid & 31;
    const int fr   = lane >> 2;
    const int fc   = (lane & 3) * 2;
    const int l15  = lane & 15;
    const int lk8  = (lane >> 4) * 8;

    const uint32_t aKh = cvta_smem(khs) + (uint32_t)((l15 * KSTR + lk8) * 2);

#pragma unroll 1
    for (int uu = 0; uu < 2; uu++) {
        const int unit = warp * 2 + uu;
        const int hd   = unit >> 2;
        const int mt   = unit & 3;
        const int r0   = mt * 16 + fr;
        const int kb   = hd * 32;

        const uint32_t vln = (uint32_t)((((lane & 7) + ((lane >> 4) & 1) * 8) * KSTR
                                         + ((lane >> 3) & 1) * 8 + kb) * 2);
        const uint32_t aVh = cvta_smem(vhs) + vln;

        float acc[8][4];
#pragma unroll
        for (int nt = 0; nt < 8; nt++)
#pragma unroll
            for (int j = 0; j < 4; j++) acc[nt][j] = 0.f;

        const __half* qbase = Qh + (size_t)(b * 64 + r0) * DIMC;
#pragma unroll
        for (int ks = 0; ks < 2; ks++) {
            const int kk = kb + ks * 16;
            uint32_t ah[4];
            ah[0] = *(const uint32_t*)(qbase + kk + fc);
            ah[1] = *(const uint32_t*)(qbase + 8 * DIMC + kk + fc);
            ah[2] = *(const uint32_t*)(qbase + kk + 8 + fc);
            ah[3] = *(const uint32_t*)(qbase + 8 * DIMC + kk + 8 + fc);
            const uint32_t kkb = (uint32_t)(kk * 2);
#pragma unroll
            for (int ntp = 0; ntp < 4; ntp++) {
                uint32_t h0, h1, h2, h3;
                ldsm4(h0, h1, h2, h3, aKh + ntp * (16 * KSTR * 2) + kkb);
                hmma(acc[2*ntp  ], ah, h0, h2);
                hmma(acc[2*ntp+1], ah, h1, h3);
            }
        }

        const __half* T = ADDT + ((size_t)(w * HEADS + hd)) * 4096;
#pragma unroll
        for (int nt = 0; nt < 8; nt++) {
            int cc = nt * 8 + fc;
            float2 t0 = h2f2(*(const uint32_t*)(T + (r0    ) * 64 + cc));
            float2 t1 = h2f2(*(const uint32_t*)(T + (r0 + 8) * 64 + cc));
            acc[nt][0] += t0.x;  acc[nt][1] += t0.y;
            acc[nt][2] += t1.x;  acc[nt][3] += t1.y;
        }

        float m0 = -1e30f, m1 = -1e30f;
#pragma unroll
        for (int nt = 0; nt < 8; nt++) {
            m0 = fmaxf(m0, fmaxf(acc[nt][0], acc[nt][1]));
            m1 = fmaxf(m1, fmaxf(acc[nt][2], acc[nt][3]));
        }
        m0 = fmaxf(m0, __shfl_xor_sync(0xffffffffu, m0, 1));
        m0 = fmaxf(m0, __shfl_xor_sync(0xffffffffu, m0, 2));
        m1 = fmaxf(m1, __shfl_xor_sync(0xffffffffu, m1, 1));
        m1 = fmaxf(m1, __shfl_xor_sync(0xffffffffu, m1, 2));

        float s0 = 0.f, s1 = 0.f;
#pragma unroll
        for (int nt = 0; nt < 8; nt++) {
            acc[nt][0] = __expf(acc[nt][0] - m0);  s0 += acc[nt][0];
            acc[nt][1] = __expf(acc[nt][1] - m0);  s0 += acc[nt][1];
            acc[nt][2] = __expf(acc[nt][2] - m1);  s1 += acc[nt][2];
            acc[nt][3] = __expf(acc[nt][3] - m1);  s1 += acc[nt][3];
        }
        s0 += __shfl_xor_sync(0xffffffffu, s0, 1);
        s0 += __shfl_xor_sync(0xffffffffu, s0, 2);
        s1 += __shfl_xor_sync(0xffffffffu, s1, 1);
        s1 += __shfl_xor_sync(0xffffffffu, s1, 2);
        float i0 = 1.f / s0, i1 = 1.f / s1;

        uint32_t ph[4][4];
#pragma unroll
        for (int kt = 0; kt < 4; kt++) {
            ph[kt][0] = cvtH2(acc[2*kt  ][0] * i0, acc[2*kt  ][1] * i0);
            ph[kt][1] = cvtH2(acc[2*kt  ][2] * i1, acc[2*kt  ][3] * i1);
            ph[kt][2] = cvtH2(acc[2*kt+1][0] * i0, acc[2*kt+1][1] * i0);
            ph[kt][3] = cvtH2(acc[2*kt+1][2] * i1, acc[2*kt+1][3] * i1);
        }

        float oacc[4][4];
#pragma unroll
        for (int dt = 0; dt < 4; dt++)
#pragma unroll
            for (int j = 0; j < 4; j++) oacc[dt][j] = 0.f;

#pragma unroll
        for (int kt = 0; kt < 4; kt++) {
            const uint32_t kof = (uint32_t)(kt * 16 * KSTR * 2);
#pragma unroll
            for (int p = 0; p < 2; p++) {
                const uint32_t off = kof + (uint32_t)(p * 16 * 2);
                uint32_t h0, h1, h2, h3;
                ldsm4t(h0, h1, h2, h3, aVh + off);
                hmma(oacc[2*p  ], ph[kt], h0, h2);
                hmma(oacc[2*p+1], ph[kt], h1, h3);
            }
        }

#pragma unroll
        for (int dt = 0; dt < 4; dt++) {
            int col = kb + dt * 8 + fc;
            *(uint32_t*)(Oh + (size_t)(b * 64 + r0    ) * DIMC + col) =
                cvtH2(oacc[dt][0], oacc[dt][1]);
            *(uint32_t*)(Oh + (size_t)(b * 64 + r0 + 8) * DIMC + col) =
                cvtH2(oacc[dt][2], oacc[dt][3]);
        }
    }
}

// ---------------------------------------------------------------------------
// launcher: Q-path (addtable + Q-GEMM) forked onto stream s1, KV on main.
// ---------------------------------------------------------------------------
extern "C" void kernel_launch(void* const* d_in, const int* in_sizes, int n_in,
                              void* d_out, int out_size)
{
    const float* x    = (const float*)d_in[0];
    const float* px   = (const float*)d_in[1];
    const float* mask = (const float*)d_in[2];
    const int*   rpi  = (const int*)  d_in[3];
    const float* rpb  = (const float*)d_in[4];
    const float* wq   = (const float*)d_in[5];
    const float* bq   = (const float*)d_in[6];
    const float* wkv  = (const float*)d_in[7];
    const float* bkv  = (const float*)d_in[8];
    const float* wp   = (const float*)d_in[9];
    const float* bp   = (const float*)d_in[10];
    float* out = (float*)d_out;

    __half *qh, *kh, *vh, *oh, *addt;
    cudaGetSymbolAddress((void**)&qh,  g_Qh);
    cudaGetSymbolAddress((void**)&kh,  g_Kh);
    cudaGetSymbolAddress((void**)&vh,  g_Vh);
    cudaGetSymbolAddress((void**)&oh,  g_Oh);
    cudaGetSymbolAddress((void**)&addt, g_ADDh);

    cudaFuncSetAttribute(gemm_hmma_kernel<0,1>,
                         cudaFuncAttributeMaxDynamicSharedMemorySize, SM_TOTAL);
    cudaFuncSetAttribute(gemm_hmma_kernel<1,0>,
                         cudaFuncAttributeMaxDynamicSharedMemorySize, SM_TOTAL);
    cudaFuncSetAttribute(kvgemm_kernel,
                         cudaFuncAttributeMaxDynamicSharedMemorySize, KV_TOTAL);
    cudaFuncSetAttribute(attn_hmma_kernel,
                         cudaFuncAttributeMaxDynamicSharedMemorySize, AT_TOTAL);

    const float qscale = 0.17677669529663687f;   // 1/sqrt(32)

    // ---- fork: Q path on s1, KV path on main stream ----
    cudaEventRecord(g_sp.eFork, 0);
    cudaStreamWaitEvent(g_sp.s1, g_sp.eFork, 0);

    addtable_kernel<<<NW * HEADS * 4096 / 256, 256, 0, g_sp.s1>>>(mask, rpi, rpb, addt);
    gemm_hmma_kernel<0,1><<<152, 512, SM_TOTAL, g_sp.s1>>>(x, wq, bq, qh, qscale);

    kvgemm_kernel<<<152, 512, KV_TOTAL>>>(px, wkv, bkv, kh, vh);

    // ---- join ----
    cudaEventRecord(g_sp.eJoin, g_sp.s1);
    cudaStreamWaitEvent(0, g_sp.eJoin, 0);

    // attention (fp16 in/out), 2 blocks/SM
    attn_hmma_kernel<<<BWIN, 384, AT_TOTAL>>>(qh, kh, vh, addt, oh);
    // out = O @ wp^T + bp  (fp16 A in, fp32 out)
    gemm_hmma_kernel<1,0><<<152, 512, SM_TOTAL>>>(oh, wp, bp, out, 1.0f);
}

// round 17
// speedup vs baseline: 1.4019x; 1.0181x over previous
#include <cuda_runtime.h>
#include <cuda_fp16.h>
#include <cstdint>

// ---------------------------------------------------------------------------
// Problem constants
// ---------------------------------------------------------------------------
#define NW        192
#define BWIN      1536
#define NTOK      64
#define DIMC      192
#define HEADS     6
#define HDIM      32
#define M_TOT     (BWIN * NTOK)     // 98304
#define MTILES    (M_TOT / 128)     // 768

// scratch (fp16 pipeline buffers)
__device__ __half g_Qh[M_TOT * DIMC];
__device__ __half g_Kh[M_TOT * DIMC];
__device__ __half g_Vh[M_TOT * DIMC];
__device__ __half g_Oh[M_TOT * DIMC];
__device__ __half g_ADDh[NW * HEADS * 4096];

// ---------------------------------------------------------------------------
// stream/event plumbing (created once at load; identical op sequence per call)
// ---------------------------------------------------------------------------
struct StreamPack {
    cudaStream_t s1 = nullptr;
    cudaEvent_t  eFork = nullptr, eJoin = nullptr;
    StreamPack() {
        cudaStreamCreateWithFlags(&s1, cudaStreamNonBlocking);
        cudaEventCreateWithFlags(&eFork, cudaEventDisableTiming);
        cudaEventCreateWithFlags(&eJoin, cudaEventDisableTiming);
    }
};
static StreamPack g_sp;

// ---------------------------------------------------------------------------
// helpers
// ---------------------------------------------------------------------------
__device__ __forceinline__ uint2 cvtH4(float4 v) {
    union { __half2 h; uint32_t u; } c0, c1;
    c0.h = __halves2half2(__float2half_rn(v.x), __float2half_rn(v.y));
    c1.h = __halves2half2(__float2half_rn(v.z), __float2half_rn(v.w));
    uint2 r; r.x = c0.u; r.y = c1.u; return r;
}
__device__ __forceinline__ uint32_t cvtH2(float p0, float p1) {
    union { __half2 h; uint32_t u; } c;
    c.h = __halves2half2(__float2half_rn(p0), __float2half_rn(p1));
    return c.u;
}
__device__ __forceinline__ void hmma(float* d, const uint32_t* a,
                                     uint32_t b0, uint32_t b1) {
    asm volatile(
        "mma.sync.aligned.m16n8k16.row.col.f32.f16.f16.f32 "
        "{%0,%1,%2,%3}, {%4,%5,%6,%7}, {%8,%9}, {%0,%1,%2,%3};"
        : "+f"(d[0]), "+f"(d[1]), "+f"(d[2]), "+f"(d[3])
        : "r"(a[0]), "r"(a[1]), "r"(a[2]), "r"(a[3]), "r"(b0), "r"(b1));
}
__device__ __forceinline__ void ldsm4(uint32_t& r0, uint32_t& r1,
                                      uint32_t& r2, uint32_t& r3, uint32_t addr) {
    asm volatile("ldmatrix.sync.aligned.m8n8.x4.shared.b16 {%0,%1,%2,%3}, [%4];"
                 : "=r"(r0), "=r"(r1), "=r"(r2), "=r"(r3) : "r"(addr));
}
__device__ __forceinline__ void ldsm4t(uint32_t& r0, uint32_t& r1,
                                       uint32_t& r2, uint32_t& r3, uint32_t addr) {
    asm volatile("ldmatrix.sync.aligned.m8n8.x4.trans.shared.b16 {%0,%1,%2,%3}, [%4];"
                 : "=r"(r0), "=r"(r1), "=r"(r2), "=r"(r3) : "r"(addr));
}
__device__ __forceinline__ uint32_t cvta_smem(const void* p) {
    return (uint32_t)__cvta_generic_to_shared(p);
}
__device__ __forceinline__ float2 h2f2(uint32_t u) {
    union { uint32_t u; __half2 h; } c; c.u = u;
    return __half22float2(c.h);
}
__device__ __forceinline__ void cpasync16(uint32_t dst, const void* src) {
    asm volatile("cp.async.cg.shared.global [%0], [%1], 16;"
                 :: "r"(dst), "l"(src) : "memory");
}

// ---------------------------------------------------------------------------
// bias table (fp16)
// ---------------------------------------------------------------------------
__global__ void __launch_bounds__(256)
addtable_kernel(const float* __restrict__ mask, const int* __restrict__ rpi,
                const float* __restrict__ rpb, __half* __restrict__ T)
{
    int idx = blockIdx.x * 256 + threadIdx.x;
    int i   = idx & 4095;
    int wh  = idx >> 12;
    int hd  = wh % HEADS;
    int w   = wh / HEADS;
    T[idx] = __float2half_rn(rpb[rpi[i] * HEADS + hd] + mask[w * 4096 + i]);
}

// ---------------------------------------------------------------------------
// HMMA GEMM (Q / out projection): Y = A @ (wscale*W)^T + wscale*bias
// M-tile 128, 512 threads, 1 CTA/SM.
// IN_F16: A fp16, else fp32.  OUT_MODE: 0 fp32, 1 fp16.
// ---------------------------------------------------------------------------
#define WSTRIDE 200
#define ASTRIDE 104

#define SM_WHI   0
#define SM_A     (SM_WHI + 192 * WSTRIDE * 2)        // 76800
#define SM_BIAS  (SM_A   + 128 * ASTRIDE * 2)        // 103424
#define SM_TOTAL (SM_BIAS + 192 * 4)                 // 104192

template<int IN_F16, int OUT_MODE>
__global__ void __launch_bounds__(512, 1)
gemm_hmma_kernel(const void* __restrict__ Ain, const float* __restrict__ W,
                 const float* __restrict__ bias, void* __restrict__ Y0,
                 float wscale)
{
    extern __shared__ char smem[];
    __half* whi = (__half*)(smem + SM_WHI);
    __half* ash = (__half*)(smem + SM_A);
    float*  bss = (float*) (smem + SM_BIAS);

    const int tid  = threadIdx.x;
    const int lane = tid & 31;
    const int warp = tid >> 5;
    const int wm   = warp & 3;
    const int wn   = warp >> 2;

    for (int i = tid; i < 192 * 48; i += 512) {
        int row = i / 48;
        int k4  = (i % 48) * 4;
        float4 v = *(const float4*)(W + (size_t)row * DIMC + k4);
        v.x *= wscale; v.y *= wscale; v.z *= wscale; v.w *= wscale;
        *(uint2*)(whi + row * WSTRIDE + k4) = cvtH4(v);
    }
    if (tid < DIMC) bss[tid] = bias[tid] * wscale;
    __syncthreads();

    const int fr  = lane >> 2;
    const int fc  = (lane & 3) * 2;
    const int l15 = lane & 15;
    const int lk8 = (lane >> 4) * 8;

    const uint32_t aA  = cvta_smem(ash) + (uint32_t)(((wm * 32 + l15) * ASTRIDE + lk8) * 2);
    const uint32_t aWh = cvta_smem(whi) + (uint32_t)(((wn * 48 + l15) * WSTRIDE + lk8) * 2);

    const float*  Af = (const float*) Ain;
    const __half* Ah = (const __half*)Ain;

    float4 pf[6];
    uint4  pg[3];
    int tile = blockIdx.x;
    if (tile < MTILES) {
        if (IN_F16) {
#pragma unroll
            for (int j = 0; j < 3; j++) {
                int i = tid + j * 512;
                int row = i / 12, c8 = (i % 12) * 8;
                pg[j] = *(const uint4*)(Ah + (size_t)(tile * 128 + row) * DIMC + c8);
            }
        } else {
#pragma unroll
            for (int j = 0; j < 6; j++) {
                int i = tid + j * 512;
                int row = i / 24, c4 = (i % 24) * 4;
                pf[j] = *(const float4*)(Af + (size_t)(tile * 128 + row) * DIMC + c4);
            }
        }
    }

    for (; tile < MTILES; tile += gridDim.x) {
        float acc[2][6][4];
#pragma unroll
        for (int mi = 0; mi < 2; mi++)
#pragma unroll
            for (int nt = 0; nt < 6; nt++)
#pragma unroll
                for (int j = 0; j < 4; j++) acc[mi][nt][j] = 0.f;

#pragma unroll 1
        for (int c = 0; c < 2; c++) {
            __syncthreads();
            if (IN_F16) {
#pragma unroll
                for (int j = 0; j < 3; j++) {
                    int i = tid + j * 512;
                    int row = i / 12, c8 = (i % 12) * 8;
                    *(uint4*)(ash + row * ASTRIDE + c8) = pg[j];
                }
            } else {
#pragma unroll
                for (int j = 0; j < 6; j++) {
                    int i = tid + j * 512;
                    int row = i / 24, c4 = (i % 24) * 4;
                    *(uint2*)(ash + row * ASTRIDE + c4) = cvtH4(pf[j]);
                }
            }
            __syncthreads();

            int nc = c + 1, ntile = tile;
            if (nc == 2) { nc = 0; ntile = tile + gridDim.x; }
            if (ntile < MTILES) {
                if (IN_F16) {
#pragma unroll
                    for (int j = 0; j < 3; j++) {
                        int i = tid + j * 512;
                        int row = i / 12, c8 = (i % 12) * 8;
                        pg[j] = *(const uint4*)(Ah + (size_t)(ntile * 128 + row) * DIMC
                                                   + nc * 96 + c8);
                    }
                } else {
#pragma unroll
                    for (int j = 0; j < 6; j++) {
                        int i = tid + j * 512;
                        int row = i / 24, c4 = (i % 24) * 4;
                        pf[j] = *(const float4*)(Af + (size_t)(ntile * 128 + row) * DIMC
                                                    + nc * 96 + c4);
                    }
                }
            }

#pragma unroll
            for (int ks = 0; ks < 6; ks++) {
                const uint32_t kkb = (uint32_t)(ks * 16 * 2);
                const uint32_t kgb = (uint32_t)((c * 96 + ks * 16) * 2);
                uint32_t fa0[4], fa1[4];
                ldsm4(fa0[0], fa0[1], fa0[2], fa0[3], aA + kkb);
                ldsm4(fa1[0], fa1[1], fa1[2], fa1[3], aA + 16 * ASTRIDE * 2 + kkb);
#pragma unroll
                for (int ntp = 0; ntp < 3; ntp++) {
                    uint32_t h0, h1, h2, h3;
                    ldsm4(h0, h1, h2, h3, aWh + ntp * (16 * WSTRIDE * 2) + kgb);
                    hmma(acc[0][2*ntp  ], fa0, h0, h2);
                    hmma(acc[0][2*ntp+1], fa0, h1, h3);
                    hmma(acc[1][2*ntp  ], fa1, h0, h2);
                    hmma(acc[1][2*ntp+1], fa1, h1, h3);
                }
            }
        }

#pragma unroll
        for (int mi = 0; mi < 2; mi++) {
            int row = tile * 128 + wm * 32 + mi * 16 + fr;
#pragma unroll
            for (int nt = 0; nt < 6; nt++) {
                int col = wn * 48 + nt * 8 + fc;
                float2 bv = *(const float2*)&bss[col];
                float v0x = acc[mi][nt][0] + bv.x, v0y = acc[mi][nt][1] + bv.y;
                float v1x = acc[mi][nt][2] + bv.x, v1y = acc[mi][nt][3] + bv.y;
                size_t o0 = (size_t)row * DIMC + col;
                size_t o1 = (size_t)(row + 8) * DIMC + col;
                if (OUT_MODE == 0) {
                    float2 r0, r1;
                    r0.x = v0x; r0.y = v0y;  r1.x = v1x; r1.y = v1y;
                    *(float2*)((float*)Y0 + o0) = r0;
                    *(float2*)((float*)Y0 + o1) = r1;
                } else {
                    *(uint32_t*)((__half*)Y0 + o0) = cvtH2(v0x, v0y);
                    *(uint32_t*)((__half*)Y0 + o1) = cvtH2(v1x, v1y);
                }
            }
        }
    }
}

// ---------------------------------------------------------------------------
// Fused KV GEMM with half-tile register prefetch (unchanged from R16)
// ---------------------------------------------------------------------------
#define KV_WS    0
#define KV_A     (KV_WS + 384 * WSTRIDE * 2)          // 153600
#define KV_BIAS  (KV_A  + 128 * WSTRIDE * 2)          // 204800
#define KV_TOTAL (KV_BIAS + 384 * 4)                  // 206336

__global__ void __launch_bounds__(512, 1)
kvgemm_kernel(const float* __restrict__ px, const float* __restrict__ wkv,
              const float* __restrict__ bkv,
              __half* __restrict__ Kh, __half* __restrict__ Vh)
{
    extern __shared__ char smem[];
    __half* ws  = (__half*)(smem + KV_WS);
    __half* ash = (__half*)(smem + KV_A);
    float*  bss = (float*) (smem + KV_BIAS);

    const int tid  = threadIdx.x;
    const int lane = tid & 31;
    const int warp = tid >> 5;
    const int wm   = warp & 3;
    const int wn   = warp >> 2;

    for (int i = tid; i < 384 * 48; i += 512) {
        int row = i / 48;
        int k4  = (i % 48) * 4;
        float4 v = *(const float4*)(wkv + (size_t)row * DIMC + k4);
        *(uint2*)(ws + row * WSTRIDE + k4) = cvtH4(v);
    }
    if (tid < 384) bss[tid] = bkv[tid];

    const int fr  = lane >> 2;
    const int fc  = (lane & 3) * 2;
    const int l15 = lane & 15;
    const int lk8 = (lane >> 4) * 8;

    const uint32_t aA = cvta_smem(ash) + (uint32_t)(((wm * 32 + l15) * WSTRIDE + lk8) * 2);
    const uint32_t aW = cvta_smem(ws)  + (uint32_t)(((wn * 48 + l15) * WSTRIDE + lk8) * 2);

    int tile = blockIdx.x;
    if (tile < MTILES) {
#pragma unroll
        for (int j = 0; j < 12; j++) {
            int i = tid + j * 512;
            int row = i / 48, c4 = (i % 48) * 4;
            float4 v = *(const float4*)(px + (size_t)(tile * 128 + row) * DIMC + c4);
            *(uint2*)(ash + row * WSTRIDE + c4) = cvtH4(v);
        }
    }
    __syncthreads();

    for (; tile < MTILES; tile += gridDim.x) {
        const int ntile = tile + gridDim.x;

        // ---- K half ----
        {
            float acc[2][6][4];
#pragma unroll
            for (int mi = 0; mi < 2; mi++)
#pragma unroll
                for (int nt = 0; nt < 6; nt++)
#pragma unroll
                    for (int j = 0; j < 4; j++) acc[mi][nt][j] = 0.f;

#pragma unroll
            for (int ks = 0; ks < 12; ks++) {
                const uint32_t kkb = (uint32_t)(ks * 16 * 2);
                uint32_t fa0[4], fa1[4];
                ldsm4(fa0[0], fa0[1], fa0[2], fa0[3], aA + kkb);
                ldsm4(fa1[0], fa1[1], fa1[2], fa1[3], aA + 16 * WSTRIDE * 2 + kkb);
#pragma unroll
                for (int ntp = 0; ntp < 3; ntp++) {
                    uint32_t h0, h1, h2, h3;
                    ldsm4(h0, h1, h2, h3, aW + ntp * (16 * WSTRIDE * 2) + kkb);
                    hmma(acc[0][2*ntp  ], fa0, h0, h2);
                    hmma(acc[0][2*ntp+1], fa0, h1, h3);
                    hmma(acc[1][2*ntp  ], fa1, h0, h2);
                    hmma(acc[1][2*ntp+1], fa1, h1, h3);
                }
            }
#pragma unroll
            for (int mi = 0; mi < 2; mi++) {
                int row = tile * 128 + wm * 32 + mi * 16 + fr;
#pragma unroll
                for (int nt = 0; nt < 6; nt++) {
                    int col = wn * 48 + nt * 8 + fc;
                    float2 bv = *(const float2*)&bss[col];
                    size_t o0 = (size_t)row * DIMC + col;
                    size_t o1 = (size_t)(row + 8) * DIMC + col;
                    *(uint32_t*)(Kh + o0) = cvtH2(acc[mi][nt][0] + bv.x,
                                                  acc[mi][nt][1] + bv.y);
                    *(uint32_t*)(Kh + o1) = cvtH2(acc[mi][nt][2] + bv.x,
                                                  acc[mi][nt][3] + bv.y);
                }
            }
        }

        // ---- prefetch rows 0..63 of next tile ----
        float4 pf[6];
        if (ntile < MTILES) {
#pragma unroll
            for (int j = 0; j < 6; j++) {
                int i = tid + j * 512;
                int row = i / 48, c4 = (i % 48) * 4;
                pf[j] = *(const float4*)(px + (size_t)(ntile * 128 + row) * DIMC + c4);
            }
        }

        // ---- V half ----
        {
            const uint32_t wbase = aW + (uint32_t)(192 * WSTRIDE * 2);
            float acc[2][6][4];
#pragma unroll
            for (int mi = 0; mi < 2; mi++)
#pragma unroll
                for (int nt = 0; nt < 6; nt++)
#pragma unroll
                    for (int j = 0; j < 4; j++) acc[mi][nt][j] = 0.f;

#pragma unroll
            for (int ks = 0; ks < 12; ks++) {
                const uint32_t kkb = (uint32_t)(ks * 16 * 2);
                uint32_t fa0[4], fa1[4];
                ldsm4(fa0[0], fa0[1], fa0[2], fa0[3], aA + kkb);
                ldsm4(fa1[0], fa1[1], fa1[2], fa1[3], aA + 16 * WSTRIDE * 2 + kkb);
#pragma unroll
                for (int ntp = 0; ntp < 3; ntp++) {
                    uint32_t h0, h1, h2, h3;
                    ldsm4(h0, h1, h2, h3, wbase + ntp * (16 * WSTRIDE * 2) + kkb);
                    hmma(acc[0][2*ntp  ], fa0, h0, h2);
                    hmma(acc[0][2*ntp+1], fa0, h1, h3);
                    hmma(acc[1][2*ntp  ], fa1, h0, h2);
                    hmma(acc[1][2*ntp+1], fa1, h1, h3);
                }
            }
#pragma unroll
            for (int mi = 0; mi < 2; mi++) {
                int row = tile * 128 + wm * 32 + mi * 16 + fr;
#pragma unroll
                for (int nt = 0; nt < 6; nt++) {
                    int col = wn * 48 + nt * 8 + fc;
                    float2 bv = *(const float2*)&bss[192 + col];
                    size_t o0 = (size_t)row * DIMC + col;
                    size_t o1 = (size_t)(row + 8) * DIMC + col;
                    *(uint32_t*)(Vh + o0) = cvtH2(acc[mi][nt][0] + bv.x,
                                                  acc[mi][nt][1] + bv.y);
                    *(uint32_t*)(Vh + o1) = cvtH2(acc[mi][nt][2] + bv.x,
                                                  acc[mi][nt][3] + bv.y);
                }
            }
        }

        __syncthreads();
        if (ntile < MTILES) {
#pragma unroll
            for (int j = 0; j < 6; j++) {
                int i = tid + j * 512;
                int row = i / 48, c4 = (i % 48) * 4;
                *(uint2*)(ash + row * WSTRIDE + c4) = cvtH4(pf[j]);
            }
#pragma unroll
            for (int j = 0; j < 6; j++) {
                int i = tid + j * 512;
                int row = 64 + i / 48, c4 = (i % 48) * 4;
                float4 v = *(const float4*)(px + (size_t)(ntile * 128 + row) * DIMC + c4);
                *(uint2*)(ash + row * WSTRIDE + c4) = cvtH4(v);
            }
        }
        __syncthreads();
    }
}

// ---------------------------------------------------------------------------
// Persistent HMMA attention: 304 blocks (2/SM), 384 threads,
// cp.async double-buffered K/V across windows.
// ---------------------------------------------------------------------------
#define KSTR 200
#define AT_ARR   (64 * KSTR * 2)        // 25600 B per tile array
#define AT_TOTAL (4 * AT_ARR)           // 102400 B (2 bufs x {K,V})

__global__ void __launch_bounds__(384, 2)
attn_hmma_kernel(const __half* __restrict__ Qh, const __half* __restrict__ Kh,
                 const __half* __restrict__ Vh, const __half* __restrict__ ADDT,
                 __half* __restrict__ Oh)
{
    extern __shared__ char smem[];
    const uint32_t sbase = cvta_smem(smem);

    const int tid  = threadIdx.x;
    const int warp = tid >> 5;
    const int lane = tid & 31;
    const int fr   = lane >> 2;
    const int fc   = (lane & 3) * 2;
    const int l15  = lane & 15;
    const int lk8  = (lane >> 4) * 8;

    // issue K/V copy for window b into buffer buf (8 cp.async / thread)
    auto issue_copy = [&](int b, int buf) {
        const uint32_t kd = sbase + (uint32_t)(buf * 2 * AT_ARR);
        const uint32_t vd = kd + AT_ARR;
#pragma unroll
        for (int j = 0; j < 4; j++) {
            int i   = tid + j * 384;
            int row = i / 24, c8 = (i % 24) * 8;
            size_t   src = (size_t)(b * 64 + row) * DIMC + c8;
            uint32_t dst = (uint32_t)((row * KSTR + c8) * 2);
            cpasync16(kd + dst, Kh + src);
            cpasync16(vd + dst, Vh + src);
        }
        asm volatile("cp.async.commit_group;" ::: "memory");
    };

    // prologue: fill buffer 0 for first window
    int b = blockIdx.x;
    if (b < BWIN) issue_copy(b, 0);

    int buf = 0;
#pragma unroll 1
    for (; b < BWIN; b += gridDim.x, buf ^= 1) {
        const int w = b % NW;

        asm volatile("cp.async.wait_group 0;" ::: "memory");
        __syncthreads();

        // prefetch next window into the other buffer (flies during compute)
        const int bn = b + gridDim.x;
        if (bn < BWIN) issue_copy(bn, buf ^ 1);

        const uint32_t kbase = sbase + (uint32_t)(buf * 2 * AT_ARR);
        const uint32_t vbase = kbase + AT_ARR;
        const uint32_t aKh = kbase + (uint32_t)((l15 * KSTR + lk8) * 2);

#pragma unroll 1
        for (int uu = 0; uu < 2; uu++) {
            const int unit = warp * 2 + uu;
            const int hd   = unit >> 2;
            const int mt   = unit & 3;
            const int r0   = mt * 16 + fr;
            const int kb   = hd * 32;

            const uint32_t vln = (uint32_t)((((lane & 7) + ((lane >> 4) & 1) * 8) * KSTR
                                             + ((lane >> 3) & 1) * 8 + kb) * 2);
            const uint32_t aVh = vbase + vln;

            // ---- S = Q K^T ----
            float acc[8][4];
#pragma unroll
            for (int nt = 0; nt < 8; nt++)
#pragma unroll
                for (int j = 0; j < 4; j++) acc[nt][j] = 0.f;

            const __half* qbase = Qh + (size_t)(b * 64 + r0) * DIMC;
#pragma unroll
            for (int ks = 0; ks < 2; ks++) {
                const int kk = kb + ks * 16;
                uint32_t ah[4];
                ah[0] = *(const uint32_t*)(qbase + kk + fc);
                ah[1] = *(const uint32_t*)(qbase + 8 * DIMC + kk + fc);
                ah[2] = *(const uint32_t*)(qbase + kk + 8 + fc);
                ah[3] = *(const uint32_t*)(qbase + 8 * DIMC + kk + 8 + fc);
                const uint32_t kkb = (uint32_t)(kk * 2);
#pragma unroll
                for (int ntp = 0; ntp < 4; ntp++) {
                    uint32_t h0, h1, h2, h3;
                    ldsm4(h0, h1, h2, h3, aKh + ntp * (16 * KSTR * 2) + kkb);
                    hmma(acc[2*ntp  ], ah, h0, h2);
                    hmma(acc[2*ntp+1], ah, h1, h3);
                }
            }

            // ---- add bias+mask table (fp16) ----
            const __half* T = ADDT + ((size_t)(w * HEADS + hd)) * 4096;
#pragma unroll
            for (int nt = 0; nt < 8; nt++) {
                int cc = nt * 8 + fc;
                float2 t0 = h2f2(*(const uint32_t*)(T + (r0    ) * 64 + cc));
                float2 t1 = h2f2(*(const uint32_t*)(T + (r0 + 8) * 64 + cc));
                acc[nt][0] += t0.x;  acc[nt][1] += t0.y;
                acc[nt][2] += t1.x;  acc[nt][3] += t1.y;
            }

            // ---- fragment softmax ----
            float m0 = -1e30f, m1 = -1e30f;
#pragma unroll
            for (int nt = 0; nt < 8; nt++) {
                m0 = fmaxf(m0, fmaxf(acc[nt][0], acc[nt][1]));
                m1 = fmaxf(m1, fmaxf(acc[nt][2], acc[nt][3]));
            }
            m0 = fmaxf(m0, __shfl_xor_sync(0xffffffffu, m0, 1));
            m0 = fmaxf(m0, __shfl_xor_sync(0xffffffffu, m0, 2));
            m1 = fmaxf(m1, __shfl_xor_sync(0xffffffffu, m1, 1));
            m1 = fmaxf(m1, __shfl_xor_sync(0xffffffffu, m1, 2));

            float s0 = 0.f, s1 = 0.f;
#pragma unroll
            for (int nt = 0; nt < 8; nt++) {
                acc[nt][0] = __expf(acc[nt][0] - m0);  s0 += acc[nt][0];
                acc[nt][1] = __expf(acc[nt][1] - m0);  s0 += acc[nt][1];
                acc[nt][2] = __expf(acc[nt][2] - m1);  s1 += acc[nt][2];
                acc[nt][3] = __expf(acc[nt][3] - m1);  s1 += acc[nt][3];
            }
            s0 += __shfl_xor_sync(0xffffffffu, s0, 1);
            s0 += __shfl_xor_sync(0xffffffffu, s0, 2);
            s1 += __shfl_xor_sync(0xffffffffu, s1, 1);
            s1 += __shfl_xor_sync(0xffffffffu, s1, 2);
            float i0 = 1.f / s0, i1 = 1.f / s1;

            // ---- repack P (single fp16) ----
            uint32_t ph[4][4];
#pragma unroll
            for (int kt = 0; kt < 4; kt++) {
                ph[kt][0] = cvtH2(acc[2*kt  ][0] * i0, acc[2*kt  ][1] * i0);
                ph[kt][1] = cvtH2(acc[2*kt  ][2] * i1, acc[2*kt  ][3] * i1);
                ph[kt][2] = cvtH2(acc[2*kt+1][0] * i0, acc[2*kt+1][1] * i0);
                ph[kt][3] = cvtH2(acc[2*kt+1][2] * i1, acc[2*kt+1][3] * i1);
            }

            // ---- O = P V  (V via ldmatrix.trans) ----
            float oacc[4][4];
#pragma unroll
            for (int dt = 0; dt < 4; dt++)
#pragma unroll
                for (int j = 0; j < 4; j++) oacc[dt][j] = 0.f;

#pragma unroll
            for (int kt = 0; kt < 4; kt++) {
                const uint32_t kof = (uint32_t)(kt * 16 * KSTR * 2);
#pragma unroll
                for (int p = 0; p < 2; p++) {
                    const uint32_t off = kof + (uint32_t)(p * 16 * 2);
                    uint32_t h0, h1, h2, h3;
                    ldsm4t(h0, h1, h2, h3, aVh + off);
                    hmma(oacc[2*p  ], ph[kt], h0, h2);
                    hmma(oacc[2*p+1], ph[kt], h1, h3);
                }
            }

            // ---- store O (fp16) ----
#pragma unroll
            for (int dt = 0; dt < 4; dt++) {
                int col = kb + dt * 8 + fc;
                *(uint32_t*)(Oh + (size_t)(b * 64 + r0    ) * DIMC + col) =
                    cvtH2(oacc[dt][0], oacc[dt][1]);
                *(uint32_t*)(Oh + (size_t)(b * 64 + r0 + 8) * DIMC + col) =
                    cvtH2(oacc[dt][2], oacc[dt][3]);
            }
        }
        __syncthreads();   // all reads of buf done before it is refilled
    }
}

// ---------------------------------------------------------------------------
// launcher: Q-path (addtable + Q-GEMM) forked onto stream s1, KV on main.
// ---------------------------------------------------------------------------
extern "C" void kernel_launch(void* const* d_in, const int* in_sizes, int n_in,
                              void* d_out, int out_size)
{
    const float* x    = (const float*)d_in[0];
    const float* px   = (const float*)d_in[1];
    const float* mask = (const float*)d_in[2];
    const int*   rpi  = (const int*)  d_in[3];
    const float* rpb  = (const float*)d_in[4];
    const float* wq   = (const float*)d_in[5];
    const float* bq   = (const float*)d_in[6];
    const float* wkv  = (const float*)d_in[7];
    const float* bkv  = (const float*)d_in[8];
    const float* wp   = (const float*)d_in[9];
    const float* bp   = (const float*)d_in[10];
    float* out = (float*)d_out;

    __half *qh, *kh, *vh, *oh, *addt;
    cudaGetSymbolAddress((void**)&qh,  g_Qh);
    cudaGetSymbolAddress((void**)&kh,  g_Kh);
    cudaGetSymbolAddress((void**)&vh,  g_Vh);
    cudaGetSymbolAddress((void**)&oh,  g_Oh);
    cudaGetSymbolAddress((void**)&addt, g_ADDh);

    cudaFuncSetAttribute(gemm_hmma_kernel<0,1>,
                         cudaFuncAttributeMaxDynamicSharedMemorySize, SM_TOTAL);
    cudaFuncSetAttribute(gemm_hmma_kernel<1,0>,
                         cudaFuncAttributeMaxDynamicSharedMemorySize, SM_TOTAL);
    cudaFuncSetAttribute(kvgemm_kernel,
                         cudaFuncAttributeMaxDynamicSharedMemorySize, KV_TOTAL);
    cudaFuncSetAttribute(attn_hmma_kernel,
                         cudaFuncAttributeMaxDynamicSharedMemorySize, AT_TOTAL);

    const float qscale = 0.17677669529663687f;   // 1/sqrt(32)

    // ---- fork: Q path on s1, KV path on main stream ----
    cudaEventRecord(g_sp.eFork, 0);
    cudaStreamWaitEvent(g_sp.s1, g_sp.eFork, 0);

    addtable_kernel<<<NW * HEADS * 4096 / 256, 256, 0, g_sp.s1>>>(mask, rpi, rpb, addt);
    gemm_hmma_kernel<0,1><<<152, 512, SM_TOTAL, g_sp.s1>>>(x, wq, bq, qh, qscale);

    kvgemm_kernel<<<152, 512, KV_TOTAL>>>(px, wkv, bkv, kh, vh);

    // ---- join ----
    cudaEventRecord(g_sp.eJoin, g_sp.s1);
    cudaStreamWaitEvent(0, g_sp.eJoin, 0);

    // persistent attention (cp.async double-buffered), 2 blocks/SM
    attn_hmma_kernel<<<304, 384, AT_TOTAL>>>(qh, kh, vh, addt, oh);
    // out = O @ wp^T + bp  (fp16 A in, fp32 out)
    gemm_hmma_kernel<1,0><<<152, 512, SM_TOTAL>>>(oh, wp, bp, out, 1.0f);
}